// round 3
// baseline (speedup 1.0000x reference)
#include <cuda_runtime.h>
#include <cstdint>

#define NN   100000
#define EE   1600000
#define ETOT (EE + NN)
#define GG   64
#define NB_SCAN 98   // ceil(NN/1024)

// ---------------- scratch (device globals: no allocation allowed) ----------------
__device__ __align__(16) int   g_cnt[NN];
__device__ __align__(16) int   g_excl[NN];
__device__ __align__(16) int   g_bsum[128];
__device__ __align__(16) int   g_rowoff[NN + 1];
__device__ __align__(16) int   g_cur[NN];
__device__ __align__(16) int   g_csr[ETOT];

__device__ __align__(16) float g_h[NN * 64];     // GEMM output (gathered by edges)
__device__ __align__(16) float g_buf[NN * 64];   // conv output (next layer input)
__device__ __align__(16) float g_ssrc[NN * 8];
__device__ __align__(16) float g_sdst[NN * 8];
__device__ __align__(16) float g_h4[NN * 4];
__device__ __align__(16) float g_o4[NN * 4];
__device__ __align__(16) float g_pool[GG * 4];
__device__ __align__(16) float g_cnt_g[GG];
__device__ int g_shift;   // 0: indices are int32; 1: indices are int64 (read low words)

// ---------------- dtype detection ----------------
// Sample odd 32-bit words of the edge buffer within its guaranteed-valid int32
// extent (2*EE words). For int64 data these are high halves of values < 2^31
// (all zero). For int32 data they are uniform src ids in [0, 1e5): ~0 chance
// that ~4096 spread samples are all zero.
__global__ void detect_kernel(const unsigned int* __restrict__ w) {
    __shared__ int any;
    if (threadIdx.x == 0) any = 0;
    __syncthreads();
    unsigned int acc = 0;
#pragma unroll
    for (int k = 0; k < 8; k++) {
        long long pos = 1LL + 2LL * ((long long)(threadIdx.x * 8 + k) * 391LL);
        if (pos < 2LL * EE) acc |= w[pos];
    }
    if (acc) atomicOr(&any, 1);
    __syncthreads();
    if (threadIdx.x == 0) g_shift = any ? 0 : 1;
}

// ---------------- CSR build ----------------
__global__ void zero_kernel() {
    int i = blockIdx.x * blockDim.x + threadIdx.x;
    if (i < NN) g_cnt[i] = 0;
    if (i < GG * 4) g_pool[i] = 0.f;
    if (i < GG) g_cnt_g[i] = 0.f;
}

__global__ void count_kernel(const int* __restrict__ ei) {
    int i = blockIdx.x * blockDim.x + threadIdx.x;
    if (i >= ETOT) return;
    int sh = g_shift;
    int dst = (i < EE) ? ei[((long long)(EE + i)) << sh] : (i - EE);
    atomicAdd(&g_cnt[dst], 1);
}

__global__ void scan1_kernel() {
    __shared__ int shm[1024];
    int tid = threadIdx.x;
    int gid = blockIdx.x * 1024 + tid;
    int v = (gid < NN) ? g_cnt[gid] : 0;
    shm[tid] = v;
    __syncthreads();
#pragma unroll
    for (int off = 1; off < 1024; off <<= 1) {
        int t = (tid >= off) ? shm[tid - off] : 0;
        __syncthreads();
        shm[tid] += t;
        __syncthreads();
    }
    if (gid < NN) g_excl[gid] = shm[tid] - v;
    if (tid == 1023) g_bsum[blockIdx.x] = shm[tid];
}

__global__ void scan2_kernel() {
    __shared__ int shm[128];
    int tid = threadIdx.x;
    int v = (tid < NB_SCAN) ? g_bsum[tid] : 0;
    shm[tid] = v;
    __syncthreads();
#pragma unroll
    for (int off = 1; off < 128; off <<= 1) {
        int t = (tid >= off) ? shm[tid - off] : 0;
        __syncthreads();
        shm[tid] += t;
        __syncthreads();
    }
    g_bsum[tid] = shm[tid] - v;  // exclusive
}

__global__ void scan3_kernel() {
    int gid = blockIdx.x * blockDim.x + threadIdx.x;
    if (gid < NN) {
        int off = g_excl[gid] + g_bsum[gid >> 10];
        g_rowoff[gid] = off;
        g_cur[gid]    = off;
    }
    if (gid == 0) g_rowoff[NN] = ETOT;
}

__global__ void scatter_kernel(const int* __restrict__ ei) {
    int i = blockIdx.x * blockDim.x + threadIdx.x;
    if (i >= ETOT) return;
    int sh = g_shift;
    int src, dst;
    if (i < EE) {
        src = ei[((long long)i) << sh];
        dst = ei[((long long)(EE + i)) << sh];
    } else {
        src = dst = i - EE;
    }
    int p = atomicAdd(&g_cur[dst], 1);
    g_csr[p] = src;
}

// ---------------- GEMMs ----------------
// conv1: [N,4] @ [4,64] -> g_h
__global__ void conv1_gemm(const float* __restrict__ x, const float* __restrict__ W) {
    int idx = blockIdx.x * blockDim.x + threadIdx.x;
    if (idx >= NN * 64) return;
    int n = idx >> 6, f = idx & 63;
    float s = 0.f;
#pragma unroll
    for (int k = 0; k < 4; k++) s += x[n * 4 + k] * W[k * 64 + f];
    g_h[idx] = s;
}

// g_buf [N,64] @ W [64,64] -> g_h. Block = 128 nodes, 256 threads, thread = 4 nodes x 8 feats
__global__ void gemm64_kernel(const float* __restrict__ W) {
    __shared__ float Ws[64 * 64];
    __shared__ float Xs[128 * 64];
    int tx = threadIdx.x;
    int n0 = blockIdx.x * 128;
    const float4* W4p = reinterpret_cast<const float4*>(W);
    float4* Ws4 = reinterpret_cast<float4*>(Ws);
#pragma unroll
    for (int i = tx; i < 1024; i += 256) Ws4[i] = W4p[i];
    const float4* in4 = reinterpret_cast<const float4*>(g_buf);
    float4* Xs4 = reinterpret_cast<float4*>(Xs);
#pragma unroll
    for (int i = tx; i < 2048; i += 256) {
        int r = i >> 4, c = i & 15;
        float4 v = make_float4(0.f, 0.f, 0.f, 0.f);
        if (n0 + r < NN) v = in4[(n0 + r) * 16 + c];
        Xs4[r * 16 + c] = v;
    }
    __syncthreads();
    int fg = tx & 7;    // feature group: f = fg*8 .. +7
    int ng = tx >> 3;   // node group: n = n0 + ng*4 .. +3
    float acc[4][8];
#pragma unroll
    for (int i = 0; i < 4; i++)
#pragma unroll
        for (int j = 0; j < 8; j++) acc[i][j] = 0.f;
#pragma unroll 8
    for (int k = 0; k < 64; k++) {
        float4 w0 = Ws4[k * 16 + fg * 2];
        float4 w1 = Ws4[k * 16 + fg * 2 + 1];
#pragma unroll
        for (int i = 0; i < 4; i++) {
            float xv = Xs[(ng * 4 + i) * 64 + k];
            acc[i][0] += xv * w0.x; acc[i][1] += xv * w0.y;
            acc[i][2] += xv * w0.z; acc[i][3] += xv * w0.w;
            acc[i][4] += xv * w1.x; acc[i][5] += xv * w1.y;
            acc[i][6] += xv * w1.z; acc[i][7] += xv * w1.w;
        }
    }
#pragma unroll
    for (int i = 0; i < 4; i++) {
        int n = n0 + ng * 4 + i;
        if (n < NN) {
            float4* op = reinterpret_cast<float4*>(g_h + n * 64 + fg * 8);
            op[0] = make_float4(acc[i][0], acc[i][1], acc[i][2], acc[i][3]);
            op[1] = make_float4(acc[i][4], acc[i][5], acc[i][6], acc[i][7]);
        }
    }
}

// conv4: g_buf [N,64] @ W [64,4] -> g_h4, warp per node
__global__ void conv4_gemm(const float* __restrict__ W) {
    int gtid = blockIdx.x * blockDim.x + threadIdx.x;
    int node = gtid >> 5;
    int lane = gtid & 31;
    if (node >= NN) return;
    float v0 = g_buf[node * 64 + lane];
    float v1 = g_buf[node * 64 + 32 + lane];
    float4 wA = reinterpret_cast<const float4*>(W)[lane];
    float4 wB = reinterpret_cast<const float4*>(W)[lane + 32];
    float p0 = v0 * wA.x + v1 * wB.x;
    float p1 = v0 * wA.y + v1 * wB.y;
    float p2 = v0 * wA.z + v1 * wB.z;
    float p3 = v0 * wA.w + v1 * wB.w;
#pragma unroll
    for (int off = 16; off > 0; off >>= 1) {
        p0 += __shfl_xor_sync(0xffffffffu, p0, off);
        p1 += __shfl_xor_sync(0xffffffffu, p1, off);
        p2 += __shfl_xor_sync(0xffffffffu, p2, off);
        p3 += __shfl_xor_sync(0xffffffffu, p3, off);
    }
    if (lane == 0) {
        float4* op = reinterpret_cast<float4*>(g_h4 + node * 4);
        *op = make_float4(p0, p1, p2, p3);
    }
}

// ---------------- attention scores s_src/s_dst ----------------
template <int H, int C, bool LAYER4>
__global__ void s_kernel(const float* __restrict__ a_src, const float* __restrict__ a_dst) {
    int idx = blockIdx.x * blockDim.x + threadIdx.x;
    if (idx >= NN * H) return;
    int node = idx / H;
    int head = idx % H;
    const float* hsrc = LAYER4 ? g_h4 : g_h;
    const float* hp = hsrc + node * (H * C) + head * C;
    const float* as = a_src + head * C;
    const float* ad = a_dst + head * C;
    float s1 = 0.f, s2 = 0.f;
#pragma unroll
    for (int c = 0; c < C; c++) {
        float v = hp[c];
        s1 += v * as[c];
        s2 += v * ad[c];
    }
    g_ssrc[idx] = s1;
    g_sdst[idx] = s2;
}

// ---------------- segment-softmax aggregation (CSR, warp-group per node) -------
// LPN lanes handle one node; each lane owns FPL consecutive features (same head).
template <int H, int C, int LPN, int FPL, bool DO_ELU, bool LAYER4>
__global__ void agg_kernel(const float* __restrict__ bias) {
    const int lane = threadIdx.x & 31;
    const int warp = (blockIdx.x * blockDim.x + threadIdx.x) >> 5;
    const int npw = 32 / LPN;
    const int node = warp * npw + lane / LPN;
    if (node >= NN) return;
    const float* __restrict__ h = LAYER4 ? g_h4 : g_h;
    float* __restrict__ out = LAYER4 ? g_o4 : g_buf;
    const int gl = lane % LPN;
    const int f0 = gl * FPL;
    const int head = f0 / C;   // with FPL=2 both features share the head (f0 even)
    const float sd = g_sdst[node * H + head];
    const int rs = g_rowoff[node];
    const int re = g_rowoff[node + 1];
    float den = 0.f, a0 = 0.f, a1 = 0.f;
    int src = (rs < re) ? g_csr[rs] : 0;
    for (int e = rs; e < re; ++e) {
        int nsrc = (e + 1 < re) ? g_csr[e + 1] : 0;
        float s = g_ssrc[src * H + head] + sd;
        s = (s > 0.f) ? s : 0.2f * s;                  // leaky_relu(0.2)
        float ex = __expf(s);                          // max-shift dropped: exact ratio
        den += ex;
        if (FPL == 2) {
            float2 hv = *reinterpret_cast<const float2*>(h + src * (H * C) + f0);
            a0 += ex * hv.x;
            a1 += ex * hv.y;
        } else {
            a0 += ex * h[src * (H * C) + f0];
        }
        src = nsrc;
    }
    float inv = 1.f / (den + 1e-16f);
    float o0 = a0 * inv + bias[f0];
    if (DO_ELU) o0 = (o0 > 0.f) ? o0 : (__expf(o0) - 1.f);
    out[node * (H * C) + f0] = o0;
    if (FPL == 2) {
        float o1 = a1 * inv + bias[f0 + 1];
        if (DO_ELU) o1 = (o1 > 0.f) ? o1 : (__expf(o1) - 1.f);
        out[node * (H * C) + f0 + 1] = o1;
    }
}

// ---------------- pooling + head ----------------
__global__ void pool_kernel(const int* __restrict__ batch) {
    int i = blockIdx.x * blockDim.x + threadIdx.x;
    int lane = threadIdx.x & 31;
    int sh = g_shift;
    int g = -1;
    float v0 = 0.f, v1 = 0.f, v2 = 0.f, v3 = 0.f;
    if (i < NN) {
        g = batch[((long long)i) << sh];
        float4 hv = *reinterpret_cast<const float4*>(g_o4 + i * 4);
        v0 = hv.x; v1 = hv.y; v2 = hv.z; v3 = hv.w;
    }
    int g0 = __shfl_sync(0xffffffffu, g, 0);
    bool uniform = __all_sync(0xffffffffu, g == g0);
    if (uniform && g0 >= 0) {
#pragma unroll
        for (int off = 16; off > 0; off >>= 1) {
            v0 += __shfl_xor_sync(0xffffffffu, v0, off);
            v1 += __shfl_xor_sync(0xffffffffu, v1, off);
            v2 += __shfl_xor_sync(0xffffffffu, v2, off);
            v3 += __shfl_xor_sync(0xffffffffu, v3, off);
        }
        if (lane == 0) {
            atomicAdd(&g_pool[g0 * 4 + 0], v0);
            atomicAdd(&g_pool[g0 * 4 + 1], v1);
            atomicAdd(&g_pool[g0 * 4 + 2], v2);
            atomicAdd(&g_pool[g0 * 4 + 3], v3);
            atomicAdd(&g_cnt_g[g0], 32.f);
        }
    } else if (i < NN) {
        atomicAdd(&g_pool[g * 4 + 0], v0);
        atomicAdd(&g_pool[g * 4 + 1], v1);
        atomicAdd(&g_pool[g * 4 + 2], v2);
        atomicAdd(&g_pool[g * 4 + 3], v3);
        atomicAdd(&g_cnt_g[g], 1.f);
    }
}

__global__ void final_kernel(const float* __restrict__ Wl, const float* __restrict__ bl,
                             float* __restrict__ out) {
    int g = threadIdx.x;
    if (g >= GG) return;
    float c = fmaxf(g_cnt_g[g], 1.f);
    float s = 0.f;
#pragma unroll
    for (int f = 0; f < 4; f++) s += (g_pool[g * 4 + f] / c) * Wl[f];
    out[g] = s + bl[0];
}

// ---------------- launch ----------------
extern "C" void kernel_launch(void* const* d_in, const int* in_sizes, int n_in,
                              void* d_out, int out_size) {
    const float* x      = (const float*)d_in[0];
    const int*   ei     = (const int*)d_in[1];
    const int*   batch  = (const int*)d_in[2];
    const float* W1     = (const float*)d_in[3];
    const float* a_src1 = (const float*)d_in[4];
    const float* a_dst1 = (const float*)d_in[5];
    const float* b1     = (const float*)d_in[6];
    const float* W2     = (const float*)d_in[7];
    const float* a_src2 = (const float*)d_in[8];
    const float* a_dst2 = (const float*)d_in[9];
    const float* b2     = (const float*)d_in[10];
    const float* W4     = (const float*)d_in[11];
    const float* a_src4 = (const float*)d_in[12];
    const float* a_dst4 = (const float*)d_in[13];
    const float* b4     = (const float*)d_in[14];
    const float* Wl     = (const float*)d_in[15];
    const float* bl     = (const float*)d_in[16];
    float* out = (float*)d_out;

    const int B = 256;
    detect_kernel<<<1, 1024>>>((const unsigned int*)ei);
    // CSR build
    zero_kernel<<<(NN + B - 1) / B, B>>>();
    count_kernel<<<(ETOT + B - 1) / B, B>>>(ei);
    scan1_kernel<<<NB_SCAN, 1024>>>();
    scan2_kernel<<<1, 128>>>();
    scan3_kernel<<<(NN + B - 1) / B, B>>>();
    scatter_kernel<<<(ETOT + B - 1) / B, B>>>(ei);

    const int gridWarpPerNode = (NN * 32 + B - 1) / B;   // 12500

    // conv1 (H=8, C=8) + ELU
    conv1_gemm<<<(NN * 64 + B - 1) / B, B>>>(x, W1);
    s_kernel<8, 8, false><<<(NN * 8 + B - 1) / B, B>>>(a_src1, a_dst1);
    agg_kernel<8, 8, 32, 2, true, false><<<gridWarpPerNode, B>>>(b1);

    // conv2 (H=1, C=64), applied twice
    gemm64_kernel<<<(NN + 127) / 128, B>>>(W2);
    s_kernel<1, 64, false><<<(NN + B - 1) / B, B>>>(a_src2, a_dst2);
    agg_kernel<1, 64, 32, 2, false, false><<<gridWarpPerNode, B>>>(b2);

    gemm64_kernel<<<(NN + 127) / 128, B>>>(W2);
    s_kernel<1, 64, false><<<(NN + B - 1) / B, B>>>(a_src2, a_dst2);
    agg_kernel<1, 64, 32, 2, false, false><<<gridWarpPerNode, B>>>(b2);

    // conv4 (H=1, C=4)
    conv4_gemm<<<gridWarpPerNode, B>>>(W4);
    s_kernel<1, 4, true><<<(NN + B - 1) / B, B>>>(a_src4, a_dst4);
    agg_kernel<1, 4, 4, 1, false, true><<<(NN * 4 + B - 1) / B, B>>>(b4);

    // global mean pool + linear head
    pool_kernel<<<(NN + B - 1) / B, B>>>(batch);
    final_kernel<<<1, 64>>>(Wl, bl, out);
}